// round 9
// baseline (speedup 1.0000x reference)
#include <cuda_runtime.h>
#include <cstdint>

// B=4, H=8, S=2048, D=8 fused attention. R7 (= R5/R6 re-bench; repeated infra failures):
//  - QPT=1, TQ=128, 512 CTAs -> 2048 warps (13.8/SM), launch_bounds(128,4) one wave
//  - per-tile k recompute (1 value/thread), double-buffered, transposed kt
//  - coalesced cp.async mask staging (double-buffered)
//  - packed f32x2 scores + PV

#define S_LEN    2048
#define D_DIM    8
#define NTHREADS 128
#define TQ       128          // queries per CTA (1 per thread)
#define TK       16           // keys per tile
#define MSTRIDE  20           // mask row stride (floats)
#define KSTRIDE  20           // kt row stride per d (floats)
#define NTILES   (S_LEN / TK) // 128

typedef unsigned long long u64;

__device__ __forceinline__ float ex2f(float x) {
    float r; asm("ex2.approx.ftz.f32 %0, %1;" : "=f"(r) : "f"(x)); return r;
}
__device__ __forceinline__ u64 fma2(u64 a, u64 b, u64 c) {
    u64 r; asm("fma.rn.f32x2 %0, %1, %2, %3;" : "=l"(r) : "l"(a), "l"(b), "l"(c)); return r;
}
__device__ __forceinline__ u64 mul2(u64 a, u64 b) {
    u64 r; asm("mul.rn.f32x2 %0, %1, %2;" : "=l"(r) : "l"(a), "l"(b)); return r;
}
__device__ __forceinline__ u64 add2(u64 a, u64 b) {
    u64 r; asm("add.rn.f32x2 %0, %1, %2;" : "=l"(r) : "l"(a), "l"(b)); return r;
}
__device__ __forceinline__ u64 pk2(float lo, float hi) {
    u64 r; asm("mov.b64 %0, {%1, %2};" : "=l"(r) : "f"(lo), "f"(hi)); return r;
}
__device__ __forceinline__ void up2(u64 v, float& lo, float& hi) {
    asm("mov.b64 {%0, %1}, %2;" : "=f"(lo), "=f"(hi) : "l"(v));
}
__device__ __forceinline__ uint32_t s2u(const void* p) {
    uint32_t a;
    asm("{ .reg .u64 t; cvta.to.shared.u64 t, %1; cvt.u32.u64 %0, t; }" : "=r"(a) : "l"(p));
    return a;
}
__device__ __forceinline__ void cp16(uint32_t dst, const void* src) {
    asm volatile("cp.async.cg.shared.global [%0], [%1], 16;" :: "r"(dst), "l"(src));
}
__device__ __forceinline__ void cpcommit() { asm volatile("cp.async.commit_group;"); }
__device__ __forceinline__ void cpwait0() { asm volatile("cp.async.wait_group 0;"); }

__global__ __launch_bounds__(NTHREADS, 4)
void attn_r7_kernel(const float* __restrict__ x,     // [B,H,S,D]
                    const float* __restrict__ mask,  // [B,1,S,S]
                    const float* __restrict__ Wq,    // [D,D]
                    const float* __restrict__ bq,    // [D]
                    const float* __restrict__ Wk,    // [D,D]
                    const float* __restrict__ bk,    // [D]
                    float* __restrict__ out)         // [B,H,S,D]
{
    extern __shared__ float smem[];
    float* mk   = smem;                        // [2 * TQ * MSTRIDE] = 5120 floats
    float* kt   = mk + 2 * TQ * MSTRIDE;       // [2 * D_DIM * KSTRIDE] = 320 floats
    float* wq_s = kt + 2 * D_DIM * KSTRIDE;    // 64
    float* bq_s = wq_s + 64;                   // 8

    const int t  = threadIdx.x;
    const int qt = blockIdx.x;
    const int h  = blockIdx.y;
    const int b  = blockIdx.z;

    const float* xb = x + ((size_t)(b * 8 + h) * S_LEN) * D_DIM;  // [S, D]
    const float* mb = mask + (size_t)b * S_LEN * S_LEN;           // [S, S]
    const int qbase = qt * TQ;

    if (t < 64) wq_s[t] = Wq[t];
    if (t < 8)  bq_s[t] = bq[t];

    // per-thread k-production assignment: one (key-in-tile, dim) value
    const int kp_key = t >> 3;        // 0..15
    const int kp_d   = t & 7;         // 0..7
    float wkr[8];
    #pragma unroll
    for (int e = 0; e < 8; e++) wkr[e] = Wk[kp_d * 8 + e];
    const float bkd = bk[kp_d];

    __syncthreads();

    const uint32_t mk_u32 = s2u(mk);

    // ---- prefetch mask tile 0: 128 rows x 4 chunks = 512 cp16, 4 per thread ----
    {
        #pragma unroll
        for (int i = 0; i < 4; i++) {
            int idx = t + i * NTHREADS;           // 0..511
            int row = idx >> 2;
            int c4  = idx & 3;
            cp16(mk_u32 + (uint32_t)(row * MSTRIDE + c4 * 4) * 4,
                 mb + (size_t)(qbase + row) * S_LEN + c4 * 4);
        }
        cpcommit();
    }

    // ---- q for my query, splatted f32x2 ----
    const float LOG2E = 1.4426950408889634f;
    const float QS    = LOG2E * 0.35355339059327373f;   // log2e / sqrt(8)
    const float MC    = -10000.0f * LOG2E;
    const u64  MC2    = pk2(MC, MC);

    u64 q[8];
    {
        const float4* xr = (const float4*)(xb + (size_t)(qbase + t) * D_DIM);
        float4 a0 = xr[0], a1 = xr[1];
        float xv[8] = {a0.x, a0.y, a0.z, a0.w, a1.x, a1.y, a1.z, a1.w};
        #pragma unroll
        for (int d = 0; d < 8; d++) {
            float acc = bq_s[d];
            #pragma unroll
            for (int e = 0; e < 8; e++)
                acc = fmaf(xv[e], wq_s[d * 8 + e], acc);
            acc *= QS;
            q[d] = pk2(acc, acc);
        }
    }

    // ---- produce k tile 0 into kt buf 0 ----
    {
        const float4* xr = (const float4*)(xb + (size_t)kp_key * D_DIM);
        float4 a0 = xr[0], a1 = xr[1];
        float acc = bkd;
        acc = fmaf(a0.x, wkr[0], acc); acc = fmaf(a0.y, wkr[1], acc);
        acc = fmaf(a0.z, wkr[2], acc); acc = fmaf(a0.w, wkr[3], acc);
        acc = fmaf(a1.x, wkr[4], acc); acc = fmaf(a1.y, wkr[5], acc);
        acc = fmaf(a1.z, wkr[6], acc); acc = fmaf(a1.w, wkr[7], acc);
        kt[kp_d * KSTRIDE + kp_key] = acc;
    }

    // ---- online softmax over keys ----
    float m = -1e30f, l = 0.0f;
    u64 nm2 = pk2(1e30f, 1e30f);          // packed (-m,-m)
    u64 a0acc = 0, a1acc = 0, a2acc = 0, a3acc = 0;

    for (int tile = 0; tile < NTILES; tile++) {
        const int buf = tile & 1;
        cpwait0();
        __syncthreads();

        if (tile + 1 < NTILES) {
            const int nbuf = buf ^ 1;
            const int nkb  = (tile + 1) * TK;
            #pragma unroll
            for (int i = 0; i < 4; i++) {
                int idx = t + i * NTHREADS;
                int row = idx >> 2;
                int c4  = idx & 3;
                cp16(mk_u32 + (uint32_t)((nbuf * TQ + row) * MSTRIDE + c4 * 4) * 4,
                     mb + (size_t)(qbase + row) * S_LEN + nkb + c4 * 4);
            }
            cpcommit();
            // produce next k tile (1 value per thread)
            const float4* xr = (const float4*)(xb + (size_t)(nkb + kp_key) * D_DIM);
            float4 aa0 = xr[0], aa1 = xr[1];
            float acc = bkd;
            acc = fmaf(aa0.x, wkr[0], acc); acc = fmaf(aa0.y, wkr[1], acc);
            acc = fmaf(aa0.z, wkr[2], acc); acc = fmaf(aa0.w, wkr[3], acc);
            acc = fmaf(aa1.x, wkr[4], acc); acc = fmaf(aa1.y, wkr[5], acc);
            acc = fmaf(aa1.z, wkr[6], acc); acc = fmaf(aa1.w, wkr[7], acc);
            kt[nbuf * D_DIM * KSTRIDE + kp_d * KSTRIDE + kp_key] = acc;
        }

        const int kb = tile * TK;
        const float* ktb  = kt + buf * D_DIM * KSTRIDE;
        const float* mrow = mk + (buf * TQ + t) * MSTRIDE;

        #pragma unroll
        for (int g = 0; g < TK / 4; g++) {
            // k quads: per d, (k_d[j..j+3]) as 2 packed pairs (broadcast LDS.128)
            u64 kq0[8], kq1[8];
            #pragma unroll
            for (int d = 0; d < 8; d++) {
                ulonglong2 kk = *(const ulonglong2*)(ktb + d * KSTRIDE + g * 4);
                kq0[d] = kk.x;
                kq1[d] = kk.y;
            }
            ulonglong2 mq = *(const ulonglong2*)(mrow + g * 4);

            u64 s01 = mul2(q[0], kq0[0]);
            u64 s23 = mul2(q[0], kq1[0]);
            #pragma unroll
            for (int d = 1; d < 8; d++) {
                s01 = fma2(q[d], kq0[d], s01);
                s23 = fma2(q[d], kq1[d], s23);
            }
            s01 = fma2(mq.x, MC2, s01);
            s23 = fma2(mq.y, MC2, s23);

            float s0, s1, s2, s3;
            up2(s01, s0, s1); up2(s23, s2, s3);

            float gmax = fmaxf(fmaxf(s0, s1), fmaxf(s2, s3));
            if (__builtin_expect(gmax > m, 0)) {
                float c = ex2f(m - gmax); m = gmax; l *= c;
                nm2 = pk2(-m, -m);
                u64 c2 = pk2(c, c);
                a0acc = mul2(a0acc, c2); a1acc = mul2(a1acc, c2);
                a2acc = mul2(a2acc, c2); a3acc = mul2(a3acc, c2);
            }

            u64 d01 = add2(s01, nm2), d23 = add2(s23, nm2);
            float e0, e1, e2, e3;
            up2(d01, e0, e1); up2(d23, e2, e3);
            float p[4] = {ex2f(e0), ex2f(e1), ex2f(e2), ex2f(e3)};
            l += p[0] + p[1] + p[2] + p[3];

            #pragma unroll
            for (int j = 0; j < 4; j++) {
                const int key = kb + g * 4 + j;
                ulonglong2 v0 = *(const ulonglong2*)(xb + key * D_DIM);      // broadcast LDG (L1)
                ulonglong2 v1 = *(const ulonglong2*)(xb + key * D_DIM + 4);
                u64 p2 = pk2(p[j], p[j]);
                a0acc = fma2(p2, v0.x, a0acc);
                a1acc = fma2(p2, v0.y, a1acc);
                a2acc = fma2(p2, v1.x, a2acc);
                a3acc = fma2(p2, v1.y, a3acc);
            }
        }
    }

    // ---- epilogue ----
    const size_t obase = (size_t)(b * 8 + h) * S_LEN;
    float inv = 1.0f / l;
    float o[8];
    up2(a0acc, o[0], o[1]); up2(a1acc, o[2], o[3]);
    up2(a2acc, o[4], o[5]); up2(a3acc, o[6], o[7]);
    float4* orow = (float4*)(out + (obase + qbase + t) * D_DIM);
    orow[0] = make_float4(o[0] * inv, o[1] * inv, o[2] * inv, o[3] * inv);
    orow[1] = make_float4(o[4] * inv, o[5] * inv, o[6] * inv, o[7] * inv);
}

extern "C" void kernel_launch(void* const* d_in, const int* in_sizes, int n_in,
                              void* d_out, int out_size) {
    const float* x    = (const float*)d_in[0];
    const float* mask = (const float*)d_in[1];
    const float* Wq   = (const float*)d_in[2];
    const float* bq   = (const float*)d_in[3];
    const float* Wk   = (const float*)d_in[4];
    const float* bk   = (const float*)d_in[5];
    float* out = (float*)d_out;

    const int smem_bytes = (2 * TQ * MSTRIDE + 2 * D_DIM * KSTRIDE + 64 + 8) * sizeof(float);

    cudaFuncSetAttribute(attn_r7_kernel,
                         cudaFuncAttributeMaxDynamicSharedMemorySize, smem_bytes);

    dim3 grid(S_LEN / TQ, 8, 4);   // (16 q-tiles, 8 heads, 4 batch) = 512 CTAs, one wave @ occ4
    dim3 block(NTHREADS);
    attn_r7_kernel<<<grid, block, smem_bytes>>>(x, mask, Wq, bq, Wk, bk, out);
}

// round 12
// speedup vs baseline: 1.3665x; 1.3665x over previous
#include <cuda_runtime.h>
#include <cstdint>

// B=4, H=8, S=2048, D=8 fused attention. R10: split-K=2 flash attention.
//  - Kernel 1: 512 CTAs (8 qt x 8 h x 4 b x 2 ksplit), QPT=2, 1024 keys/CTA.
//    R4's proven inner loop (packed f32x2, cp.async mask staging, per-tile k recompute).
//    Writes unnormalized partials (m, l, acc[8]) to __device__ scratch.
//  - Kernel 2: merges the 2 splits per query (65536 threads).

#define S_LEN    2048
#define D_DIM    8
#define NTHREADS 128
#define TQ       256          // queries per CTA (2 per thread)
#define TK       16           // keys per tile
#define KSPLIT   2
#define KEYS_PER (S_LEN / KSPLIT)        // 1024
#define MSTRIDE  20           // mask row stride (floats)
#define KSTRIDE  20           // kt row stride per d (floats)
#define NTILES   (KEYS_PER / TK)         // 64
#define NQ_TOT   (4 * 8 * S_LEN)         // 65536

typedef unsigned long long u64;

__device__ float g_m[KSPLIT][NQ_TOT];
__device__ float g_l[KSPLIT][NQ_TOT];
__device__ float g_acc[KSPLIT][NQ_TOT][D_DIM];

__device__ __forceinline__ float ex2f(float x) {
    float r; asm("ex2.approx.ftz.f32 %0, %1;" : "=f"(r) : "f"(x)); return r;
}
__device__ __forceinline__ u64 fma2(u64 a, u64 b, u64 c) {
    u64 r; asm("fma.rn.f32x2 %0, %1, %2, %3;" : "=l"(r) : "l"(a), "l"(b), "l"(c)); return r;
}
__device__ __forceinline__ u64 mul2(u64 a, u64 b) {
    u64 r; asm("mul.rn.f32x2 %0, %1, %2;" : "=l"(r) : "l"(a), "l"(b)); return r;
}
__device__ __forceinline__ u64 add2(u64 a, u64 b) {
    u64 r; asm("add.rn.f32x2 %0, %1, %2;" : "=l"(r) : "l"(a), "l"(b)); return r;
}
__device__ __forceinline__ u64 pk2(float lo, float hi) {
    u64 r; asm("mov.b64 %0, {%1, %2};" : "=l"(r) : "f"(lo), "f"(hi)); return r;
}
__device__ __forceinline__ void up2(u64 v, float& lo, float& hi) {
    asm("mov.b64 {%0, %1}, %2;" : "=f"(lo), "=f"(hi) : "l"(v));
}
__device__ __forceinline__ uint32_t s2u(const void* p) {
    uint32_t a;
    asm("{ .reg .u64 t; cvta.to.shared.u64 t, %1; cvt.u32.u64 %0, t; }" : "=r"(a) : "l"(p));
    return a;
}
__device__ __forceinline__ void cp16(uint32_t dst, const void* src) {
    asm volatile("cp.async.cg.shared.global [%0], [%1], 16;" :: "r"(dst), "l"(src));
}
__device__ __forceinline__ void cpcommit() { asm volatile("cp.async.commit_group;"); }
__device__ __forceinline__ void cpwait0() { asm volatile("cp.async.wait_group 0;"); }

__global__ __launch_bounds__(NTHREADS, 3)
void attn_r10_partial(const float* __restrict__ x,     // [B,H,S,D]
                      const float* __restrict__ mask,  // [B,1,S,S]
                      const float* __restrict__ Wq,    // [D,D]
                      const float* __restrict__ bq,    // [D]
                      const float* __restrict__ Wk,    // [D,D]
                      const float* __restrict__ bk)    // [D]
{
    extern __shared__ float smem[];
    float* mk   = smem;                        // [2 * TQ * MSTRIDE] = 10240 floats
    float* kt   = mk + 2 * TQ * MSTRIDE;       // [2 * D_DIM * KSTRIDE] = 320 floats
    float* wq_s = kt + 2 * D_DIM * KSTRIDE;    // 64
    float* bq_s = wq_s + 64;                   // 8

    const int t  = threadIdx.x;
    const int qt = blockIdx.x;
    const int h  = blockIdx.y;
    const int b  = blockIdx.z >> 1;
    const int ks = blockIdx.z & 1;
    const int kbase = ks * KEYS_PER;

    const float* xb = x + ((size_t)(b * 8 + h) * S_LEN) * D_DIM;  // [S, D]
    const float* mb = mask + (size_t)b * S_LEN * S_LEN;           // [S, S]
    const int qbase = qt * TQ;

    if (t < 64) wq_s[t] = Wq[t];
    if (t < 8)  bq_s[t] = bq[t];

    // per-thread k-production assignment: one (key-in-tile, dim) value
    const int kp_key = t >> 3;        // 0..15
    const int kp_d   = t & 7;         // 0..7
    float wkr[8];
    #pragma unroll
    for (int e = 0; e < 8; e++) wkr[e] = Wk[kp_d * 8 + e];
    const float bkd = bk[kp_d];

    __syncthreads();

    const uint32_t mk_u32 = s2u(mk);

    // ---- prefetch mask tile 0 (256 rows x 4 chunks = 1024 cp16, 8/thread) ----
    {
        #pragma unroll
        for (int i = 0; i < 8; i++) {
            int idx = t + i * NTHREADS;
            int row = idx >> 2;
            int c4  = idx & 3;
            cp16(mk_u32 + (uint32_t)(row * MSTRIDE + c4 * 4) * 4,
                 mb + (size_t)(qbase + row) * S_LEN + kbase + c4 * 4);
        }
        cpcommit();
    }

    // ---- q for my two queries, splatted f32x2 ----
    const float LOG2E = 1.4426950408889634f;
    const float QS    = LOG2E * 0.35355339059327373f;   // log2e / sqrt(8)
    const float MC    = -10000.0f * LOG2E;
    const u64  MC2    = pk2(MC, MC);

    u64 qA[8], qB[8];
    #pragma unroll
    for (int w = 0; w < 2; w++) {
        int qi = qbase + t + w * 128;
        const float4* xr = (const float4*)(xb + (size_t)qi * D_DIM);
        float4 a0 = xr[0], a1 = xr[1];
        float xv[8] = {a0.x, a0.y, a0.z, a0.w, a1.x, a1.y, a1.z, a1.w};
        u64* qq = w ? qB : qA;
        #pragma unroll
        for (int d = 0; d < 8; d++) {
            float acc = bq_s[d];
            #pragma unroll
            for (int e = 0; e < 8; e++)
                acc = fmaf(xv[e], wq_s[d * 8 + e], acc);
            acc *= QS;
            qq[d] = pk2(acc, acc);
        }
    }

    // ---- produce k tile 0 into kt buf 0 ----
    {
        const float4* xr = (const float4*)(xb + (size_t)(kbase + kp_key) * D_DIM);
        float4 a0 = xr[0], a1 = xr[1];
        float acc = bkd;
        acc = fmaf(a0.x, wkr[0], acc); acc = fmaf(a0.y, wkr[1], acc);
        acc = fmaf(a0.z, wkr[2], acc); acc = fmaf(a0.w, wkr[3], acc);
        acc = fmaf(a1.x, wkr[4], acc); acc = fmaf(a1.y, wkr[5], acc);
        acc = fmaf(a1.z, wkr[6], acc); acc = fmaf(a1.w, wkr[7], acc);
        kt[kp_d * KSTRIDE + kp_key] = acc;
    }

    // ---- online softmax over this CTA's 1024 keys ----
    float mA = -1e30f, lA = 0.0f, mB = -1e30f, lB = 0.0f;
    u64 nmA2 = pk2(1e30f, 1e30f), nmB2 = nmA2;
    u64 aA0 = 0, aA1 = 0, aA2 = 0, aA3 = 0;
    u64 aB0 = 0, aB1 = 0, aB2 = 0, aB3 = 0;

    for (int tile = 0; tile < NTILES; tile++) {
        const int buf = tile & 1;
        cpwait0();
        __syncthreads();

        if (tile + 1 < NTILES) {
            const int nbuf = buf ^ 1;
            const int nkb  = kbase + (tile + 1) * TK;
            #pragma unroll
            for (int i = 0; i < 8; i++) {
                int idx = t + i * NTHREADS;
                int row = idx >> 2;
                int c4  = idx & 3;
                cp16(mk_u32 + (uint32_t)((nbuf * TQ + row) * MSTRIDE + c4 * 4) * 4,
                     mb + (size_t)(qbase + row) * S_LEN + nkb + c4 * 4);
            }
            cpcommit();
            const float4* xr = (const float4*)(xb + (size_t)(nkb + kp_key) * D_DIM);
            float4 aa0 = xr[0], aa1 = xr[1];
            float acc = bkd;
            acc = fmaf(aa0.x, wkr[0], acc); acc = fmaf(aa0.y, wkr[1], acc);
            acc = fmaf(aa0.z, wkr[2], acc); acc = fmaf(aa0.w, wkr[3], acc);
            acc = fmaf(aa1.x, wkr[4], acc); acc = fmaf(aa1.y, wkr[5], acc);
            acc = fmaf(aa1.z, wkr[6], acc); acc = fmaf(aa1.w, wkr[7], acc);
            kt[nbuf * D_DIM * KSTRIDE + kp_d * KSTRIDE + kp_key] = acc;
        }

        const int kb = kbase + tile * TK;
        const float* ktb   = kt + buf * D_DIM * KSTRIDE;
        const float* mrowA = mk + (buf * TQ + t) * MSTRIDE;
        const float* mrowB = mrowA + 128 * MSTRIDE;

        #pragma unroll
        for (int g = 0; g < TK / 4; g++) {
            u64 kq0[8], kq1[8];
            #pragma unroll
            for (int d = 0; d < 8; d++) {
                ulonglong2 kk = *(const ulonglong2*)(ktb + d * KSTRIDE + g * 4);
                kq0[d] = kk.x;
                kq1[d] = kk.y;
            }
            ulonglong2 mqA = *(const ulonglong2*)(mrowA + g * 4);
            ulonglong2 mqB = *(const ulonglong2*)(mrowB + g * 4);

            u64 s01A = mul2(qA[0], kq0[0]);
            u64 s23A = mul2(qA[0], kq1[0]);
            u64 s01B = mul2(qB[0], kq0[0]);
            u64 s23B = mul2(qB[0], kq1[0]);
            #pragma unroll
            for (int d = 1; d < 8; d++) {
                s01A = fma2(qA[d], kq0[d], s01A);
                s23A = fma2(qA[d], kq1[d], s23A);
                s01B = fma2(qB[d], kq0[d], s01B);
                s23B = fma2(qB[d], kq1[d], s23B);
            }
            s01A = fma2(mqA.x, MC2, s01A);
            s23A = fma2(mqA.y, MC2, s23A);
            s01B = fma2(mqB.x, MC2, s01B);
            s23B = fma2(mqB.y, MC2, s23B);

            float s0A, s1A, s2A, s3A, s0B, s1B, s2B, s3B;
            up2(s01A, s0A, s1A); up2(s23A, s2A, s3A);
            up2(s01B, s0B, s1B); up2(s23B, s2B, s3B);

            float gA = fmaxf(fmaxf(s0A, s1A), fmaxf(s2A, s3A));
            if (__builtin_expect(gA > mA, 0)) {
                float c = ex2f(mA - gA); mA = gA; lA *= c;
                nmA2 = pk2(-mA, -mA);
                u64 c2 = pk2(c, c);
                aA0 = mul2(aA0, c2); aA1 = mul2(aA1, c2);
                aA2 = mul2(aA2, c2); aA3 = mul2(aA3, c2);
            }
            float gB = fmaxf(fmaxf(s0B, s1B), fmaxf(s2B, s3B));
            if (__builtin_expect(gB > mB, 0)) {
                float c = ex2f(mB - gB); mB = gB; lB *= c;
                nmB2 = pk2(-mB, -mB);
                u64 c2 = pk2(c, c);
                aB0 = mul2(aB0, c2); aB1 = mul2(aB1, c2);
                aB2 = mul2(aB2, c2); aB3 = mul2(aB3, c2);
            }

            u64 d01A = add2(s01A, nmA2), d23A = add2(s23A, nmA2);
            u64 d01B = add2(s01B, nmB2), d23B = add2(s23B, nmB2);
            float e0A, e1A, e2A, e3A, e0B, e1B, e2B, e3B;
            up2(d01A, e0A, e1A); up2(d23A, e2A, e3A);
            up2(d01B, e0B, e1B); up2(d23B, e2B, e3B);
            float pA[4] = {ex2f(e0A), ex2f(e1A), ex2f(e2A), ex2f(e3A)};
            float pB[4] = {ex2f(e0B), ex2f(e1B), ex2f(e2B), ex2f(e3B)};
            lA += pA[0] + pA[1] + pA[2] + pA[3];
            lB += pB[0] + pB[1] + pB[2] + pB[3];

            #pragma unroll
            for (int j = 0; j < 4; j++) {
                const int key = kb + g * 4 + j;
                ulonglong2 v0 = *(const ulonglong2*)(xb + key * D_DIM);
                ulonglong2 v1 = *(const ulonglong2*)(xb + key * D_DIM + 4);
                u64 pA2 = pk2(pA[j], pA[j]);
                aA0 = fma2(pA2, v0.x, aA0);
                aA1 = fma2(pA2, v0.y, aA1);
                aA2 = fma2(pA2, v1.x, aA2);
                aA3 = fma2(pA2, v1.y, aA3);
                u64 pB2 = pk2(pB[j], pB[j]);
                aB0 = fma2(pB2, v0.x, aB0);
                aB1 = fma2(pB2, v0.y, aB1);
                aB2 = fma2(pB2, v1.x, aB2);
                aB3 = fma2(pB2, v1.y, aB3);
            }
        }
    }

    // ---- write unnormalized partials ----
    const int qid0 = (b * 8 + h) * S_LEN + qbase + t;        // query A
    {
        float o[8];
        up2(aA0, o[0], o[1]); up2(aA1, o[2], o[3]);
        up2(aA2, o[4], o[5]); up2(aA3, o[6], o[7]);
        g_m[ks][qid0] = mA;
        g_l[ks][qid0] = lA;
        float4* pa = (float4*)g_acc[ks][qid0];
        pa[0] = make_float4(o[0], o[1], o[2], o[3]);
        pa[1] = make_float4(o[4], o[5], o[6], o[7]);
    }
    const int qid1 = qid0 + 128;                              // query B
    {
        float o[8];
        up2(aB0, o[0], o[1]); up2(aB1, o[2], o[3]);
        up2(aB2, o[4], o[5]); up2(aB3, o[6], o[7]);
        g_m[ks][qid1] = mB;
        g_l[ks][qid1] = lB;
        float4* pb = (float4*)g_acc[ks][qid1];
        pb[0] = make_float4(o[0], o[1], o[2], o[3]);
        pb[1] = make_float4(o[4], o[5], o[6], o[7]);
    }
}

__global__ __launch_bounds__(256)
void attn_r10_reduce(float* __restrict__ out)   // [B,H,S,D] flat: qid*8+d
{
    const int qid = blockIdx.x * 256 + threadIdx.x;

    float m0 = g_m[0][qid], m1 = g_m[1][qid];
    float l0 = g_l[0][qid], l1 = g_l[1][qid];
    float M  = fmaxf(m0, m1);
    float c0 = ex2f(m0 - M);     // m is log2-domain
    float c1 = ex2f(m1 - M);
    float inv = 1.0f / (l0 * c0 + l1 * c1);
    float w0 = c0 * inv, w1 = c1 * inv;

    const float4* a0 = (const float4*)g_acc[0][qid];
    const float4* a1 = (const float4*)g_acc[1][qid];
    float4 x0 = a0[0], x1 = a0[1];
    float4 y0 = a1[0], y1 = a1[1];

    float4* orow = (float4*)(out + (size_t)qid * D_DIM);
    orow[0] = make_float4(x0.x * w0 + y0.x * w1, x0.y * w0 + y0.y * w1,
                          x0.z * w0 + y0.z * w1, x0.w * w0 + y0.w * w1);
    orow[1] = make_float4(x1.x * w0 + y1.x * w1, x1.y * w0 + y1.y * w1,
                          x1.z * w0 + y1.z * w1, x1.w * w0 + y1.w * w1);
}

extern "C" void kernel_launch(void* const* d_in, const int* in_sizes, int n_in,
                              void* d_out, int out_size) {
    const float* x    = (const float*)d_in[0];
    const float* mask = (const float*)d_in[1];
    const float* Wq   = (const float*)d_in[2];
    const float* bq   = (const float*)d_in[3];
    const float* Wk   = (const float*)d_in[4];
    const float* bk   = (const float*)d_in[5];
    float* out = (float*)d_out;

    const int smem_bytes = (2 * TQ * MSTRIDE + 2 * D_DIM * KSTRIDE + 64 + 8) * sizeof(float);

    cudaFuncSetAttribute(attn_r10_partial,
                         cudaFuncAttributeMaxDynamicSharedMemorySize, smem_bytes);

    dim3 grid(S_LEN / TQ, 8, 4 * KSPLIT);   // (8 qt, 8 h, 8 b*ks) = 512 CTAs
    dim3 block(NTHREADS);
    attn_r10_partial<<<grid, block, smem_bytes>>>(x, mask, Wq, bq, Wk, bk);

    attn_r10_reduce<<<NQ_TOT / 256, 256>>>(out);
}